// round 3
// baseline (speedup 1.0000x reference)
#include <cuda_runtime.h>
#include <math.h>

typedef unsigned long long ull;

// ---------------- static scratch (no runtime allocation allowed) ----------------
#define MAXN 100000
#define MAXE 500000
#define MAXNODES 1000000

__device__ int   g_assoc[MAXNODES];
__device__ float g_Q  [(size_t)MAXN*100];
__device__ float g_K  [(size_t)MAXN*100];
__device__ float g_V  [(size_t)MAXN*100];
__device__ float g_AGG[(size_t)MAXN*100];      // skip output, then scatter-accumulated
__device__ float g_EPROJ[(size_t)MAXE*100];
__device__ float g_alpha[(size_t)MAXE*2];
__device__ float g_aexp [(size_t)MAXE*2];
__device__ float g_amax [(size_t)MAXN*2];
__device__ float g_aden [(size_t)MAXN*2];

// ---------------- f32x2 packed-FMA helpers (full-rate FFMA on sm_103a) ----------
__device__ __forceinline__ ull pack2(float x, float y) {
    ull r; asm("mov.b64 %0,{%1,%2};" : "=l"(r) : "f"(x), "f"(y)); return r;
}
__device__ __forceinline__ float2 unpack2(ull v) {
    float2 r; asm("mov.b64 {%0,%1},%2;" : "=f"(r.x), "=f"(r.y) : "l"(v)); return r;
}
__device__ __forceinline__ void ffma2(ull& d, ull a, ull b) {
    asm("fma.rn.f32x2 %0,%1,%2,%3;" : "=l"(d) : "l"(a), "l"(b), "l"(d));
}

__device__ __forceinline__ void atomicMaxF(float* addr, float v) {
    if (v >= 0.f) atomicMax((int*)addr, __float_as_int(v));
    else          atomicMin((unsigned int*)addr, (unsigned int)__float_as_int(v));
}

// ---------------- init: assoc=0, amax=-inf, aden=0 ------------------------------
__global__ void init_kernel(int N) {
    int i = blockIdx.x * blockDim.x + threadIdx.x;
    if (i < MAXNODES) g_assoc[i] = 0;
    if (i < 2 * N) { g_amax[i] = -3.402823466e38f; g_aden[i] = 0.f; }
}

__global__ void assoc_kernel(const int* __restrict__ n_id, int N) {
    int i = blockIdx.x * blockDim.x + threadIdx.x;
    if (i < N) g_assoc[n_id[i]] = i;
}

// ---------------- fused Q/K/V/skip GEMM: C = z @ W^T + b -------------------------
// grid.x tiles rows (BM=128), grid.y in {0,1,2,3} selects {Q,K,V,AGG(skip)}.
// block = 320 threads: 32 rowgroups (TM=4) x 10 colgroups (TN=10 as 5 f32x2).
#define GBM 128
#define GTHREADS 320
__global__ void __launch_bounds__(GTHREADS, 2) qkvs_kernel(
    const float* __restrict__ z,
    const float* __restrict__ W0, const float* __restrict__ b0,
    const float* __restrict__ W1, const float* __restrict__ b1,
    const float* __restrict__ W2, const float* __restrict__ b2,
    const float* __restrict__ W3, const float* __restrict__ b3,
    int N)
{
    extern __shared__ float sm[];
    float* a_s    = sm;                 // [100][128] k-major
    float* b_s    = sm + 100 * GBM;     // [100][100] k-major (W^T)
    float* bias_s = b_s + 100 * 100;    // [100]

    const float* W; const float* bias; float* out;
    switch (blockIdx.y) {
        case 0:  W = W0; bias = b0; out = g_Q;   break;
        case 1:  W = W1; bias = b1; out = g_K;   break;
        case 2:  W = W2; bias = b2; out = g_V;   break;
        default: W = W3; bias = b3; out = g_AGG; break;
    }
    int tid  = threadIdx.x;
    int row0 = blockIdx.x * GBM;

    for (int idx = tid; idx < GBM * 100; idx += GTHREADS) {
        int r = idx / 100, k = idx - r * 100;
        int gr = row0 + r;
        a_s[k * GBM + r] = (gr < N) ? z[gr * 100 + k] : 0.f;
    }
    for (int idx = tid; idx < 10000; idx += GTHREADS) {
        int o = idx / 100, k = idx - o * 100;
        b_s[k * 100 + o] = W[idx];
    }
    if (tid < 100) bias_s[tid] = bias[tid];
    __syncthreads();

    int cg = tid % 10, rg = tid / 10;
    int rb = rg * 4, cb = cg * 10;
    ull acc[4][5];
    #pragma unroll
    for (int i = 0; i < 4; i++)
        #pragma unroll
        for (int j = 0; j < 5; j++) acc[i][j] = 0ull;

    #pragma unroll 4
    for (int k = 0; k < 100; k++) {
        float4 av = *(const float4*)(a_s + k * GBM + rb);
        ull a2[4] = { pack2(av.x, av.x), pack2(av.y, av.y),
                      pack2(av.z, av.z), pack2(av.w, av.w) };
        const ull* bp = (const ull*)(b_s + k * 100 + cb);
        ull b2[5];
        #pragma unroll
        for (int j = 0; j < 5; j++) b2[j] = bp[j];
        #pragma unroll
        for (int i = 0; i < 4; i++)
            #pragma unroll
            for (int j = 0; j < 5; j++) ffma2(acc[i][j], a2[i], b2[j]);
    }

    #pragma unroll
    for (int i = 0; i < 4; i++) {
        int gr = row0 + rb + i;
        if (gr < N) {
            float2* op = (float2*)(out + (size_t)gr * 100 + cb);
            #pragma unroll
            for (int j = 0; j < 5; j++) {
                float2 r = unpack2(acc[i][j]);
                r.x += bias_s[cb + 2 * j];
                r.y += bias_s[cb + 2 * j + 1];
                op[j] = r;
            }
        }
    }
}

// ---------------- edge projection GEMM: e_proj = edge_attr @ We^T ----------------
// edge_attr row = [cos(rel_t*tw + tb) (100), msg (1)] generated directly in smem.
__global__ void __launch_bounds__(GTHREADS, 2) eproj_kernel(
    const float* __restrict__ lu, const float* __restrict__ t,
    const float* __restrict__ msg,
    const float* __restrict__ tw, const float* __restrict__ tb,
    const float* __restrict__ We, const int* __restrict__ ei, int E)
{
    extern __shared__ float sm[];
    float* a_s  = sm;                   // [101][128] k-major (generated)
    float* b_s  = sm + 101 * GBM;       // [101][100] k-major (We^T)
    float* tw_s = b_s + 101 * 100;      // [100]
    float* tb_s = tw_s + 100;           // [100]
    __shared__ float rel_s[GBM];

    int tid  = threadIdx.x;
    int row0 = blockIdx.x * GBM;

    if (tid < GBM) {
        int e = row0 + tid; float rv = 0.f, mv = 0.f;
        if (e < E) { int s = ei[e]; rv = lu[s] - t[e]; mv = msg[e]; }
        rel_s[tid] = rv;
        a_s[100 * GBM + tid] = mv;      // k=100 row = msg
    }
    if (tid >= GBM && tid < GBM + 100) {
        int k = tid - GBM; tw_s[k] = tw[k]; tb_s[k] = tb[k];
    }
    for (int idx = tid; idx < 10100; idx += GTHREADS) {
        int o = idx / 101, k = idx - o * 101;
        b_s[k * 100 + o] = We[idx];
    }
    __syncthreads();

    for (int idx = tid; idx < 100 * GBM; idx += GTHREADS) {
        int k = idx >> 7, r = idx & (GBM - 1);
        a_s[idx] = cosf(fmaf(rel_s[r], tw_s[k], tb_s[k]));
    }
    __syncthreads();

    int cg = tid % 10, rg = tid / 10;
    int rb = rg * 4, cb = cg * 10;
    ull acc[4][5];
    #pragma unroll
    for (int i = 0; i < 4; i++)
        #pragma unroll
        for (int j = 0; j < 5; j++) acc[i][j] = 0ull;

    #pragma unroll 4
    for (int k = 0; k < 101; k++) {
        float4 av = *(const float4*)(a_s + k * GBM + rb);
        ull a2[4] = { pack2(av.x, av.x), pack2(av.y, av.y),
                      pack2(av.z, av.z), pack2(av.w, av.w) };
        const ull* bp = (const ull*)(b_s + k * 100 + cb);
        ull b2[5];
        #pragma unroll
        for (int j = 0; j < 5; j++) b2[j] = bp[j];
        #pragma unroll
        for (int i = 0; i < 4; i++)
            #pragma unroll
            for (int j = 0; j < 5; j++) ffma2(acc[i][j], a2[i], b2[j]);
    }

    #pragma unroll
    for (int i = 0; i < 4; i++) {
        int e = row0 + rb + i;
        if (e < E) {
            float2* op = (float2*)(g_EPROJ + (size_t)e * 100 + cb);
            #pragma unroll
            for (int j = 0; j < 5; j++) op[j] = unpack2(acc[i][j]);
        }
    }
}

// ---------------- alpha = q[dst] . (k[src] + e_proj) / sqrt(50), atomicMax -------
__global__ void alpha_kernel(const int* __restrict__ ei, int E)
{
    int gw   = (blockIdx.x * blockDim.x + threadIdx.x) >> 5;
    int lane = threadIdx.x & 31;
    if (gw >= E) return;
    int s = ei[gw], d = ei[E + gw];
    const float* kr = g_K + (size_t)s * 100;
    const float* qr = g_Q + (size_t)d * 100;
    const float* ep = g_EPROJ + (size_t)gw * 100;
    float a0 = 0.f, a1 = 0.f;
    for (int c = lane; c < 100; c += 32) {
        float v = qr[c] * (kr[c] + ep[c]);
        if (c < 50) a0 += v; else a1 += v;
    }
    #pragma unroll
    for (int o = 16; o; o >>= 1) {
        a0 += __shfl_xor_sync(0xffffffffu, a0, o);
        a1 += __shfl_xor_sync(0xffffffffu, a1, o);
    }
    if (lane == 0) {
        const float inv = 0.14142135623730951f; // 1/sqrt(50)
        a0 *= inv; a1 *= inv;
        g_alpha[2 * gw]     = a0;
        g_alpha[2 * gw + 1] = a1;
        atomicMaxF(&g_amax[2 * d],     a0);
        atomicMaxF(&g_amax[2 * d + 1], a1);
    }
}

// ---------------- a = exp(alpha - amax[dst]); aden += a --------------------------
__global__ void aexp_kernel(const int* __restrict__ ei, int E)
{
    int i = blockIdx.x * blockDim.x + threadIdx.x;
    if (i >= 2 * E) return;
    int e = i >> 1, h = i & 1;
    int d = ei[E + e];
    float a = expf(g_alpha[i] - g_amax[2 * d + h]);
    g_aexp[i] = a;
    atomicAdd(&g_aden[2 * d + h], a);
}

// ---------------- agg[dst] += (v[src] + e_proj) * a/aden (float4 red) ------------
__global__ void scatter_kernel(const int* __restrict__ ei, int E)
{
    int gw   = (blockIdx.x * blockDim.x + threadIdx.x) >> 5;
    int lane = threadIdx.x & 31;
    if (gw >= E || lane >= 25) return;
    int s = ei[gw], d = ei[E + gw];
    float c0 = g_aexp[2 * gw]     / g_aden[2 * d];
    float c1 = g_aexp[2 * gw + 1] / g_aden[2 * d + 1];
    int col = lane * 4;
    float4 v4 = *(const float4*)(g_V + (size_t)s * 100 + col);
    float4 e4 = *(const float4*)(g_EPROJ + (size_t)gw * 100 + col);
    float4 r;
    r.x = (v4.x + e4.x) * ((col + 0) < 50 ? c0 : c1);
    r.y = (v4.y + e4.y) * ((col + 1) < 50 ? c0 : c1);
    r.z = (v4.z + e4.z) * ((col + 2) < 50 ? c0 : c1);
    r.w = (v4.w + e4.w) * ((col + 3) < 50 ? c0 : c1);
    atomicAdd((float4*)(g_AGG + (size_t)d * 100 + col), r);
}

// ---------------- link predictor -------------------------------------------------
__global__ void __launch_bounds__(128) linkpred_kernel(
    const float* __restrict__ Wsrc, const float* __restrict__ bsrc,
    const float* __restrict__ Wdst, const float* __restrict__ bdst,
    const float* __restrict__ Wf,   const float* __restrict__ bf,
    const int* __restrict__ src, const int* __restrict__ dst,
    float* __restrict__ out, int B)
{
    extern __shared__ float sm[];
    float* Ws   = sm;                 // [100][101] padded (conflict-free)
    float* Wd   = Ws + 100 * 101;
    float* bsum = Wd + 100 * 101;     // bsrc+bdst
    float* wf   = bsum + 100;
    float* zrow = wf + 100;           // 4 warps * 200

    int tid = threadIdx.x, lane = tid & 31, warp = tid >> 5;
    for (int idx = tid; idx < 10000; idx += 128) {
        int o = idx / 100, k = idx - o * 100;
        Ws[o * 101 + k] = Wsrc[idx];
        Wd[o * 101 + k] = Wdst[idx];
    }
    if (tid < 100) { bsum[tid] = bsrc[tid] + bdst[tid]; wf[tid] = Wf[tid]; }
    __syncthreads();

    float bf0 = bf[0];
    float* zs = zrow + warp * 200;
    float* zd = zs + 100;

    for (int p = blockIdx.x * 4 + warp; p < B; p += gridDim.x * 4) {
        int sp = g_assoc[src[p]];
        int dp = g_assoc[dst[p]];
        for (int c = lane; c < 100; c += 32) {
            zs[c] = g_AGG[(size_t)sp * 100 + c];
            zd[c] = g_AGG[(size_t)dp * 100 + c];
        }
        __syncwarp();
        float acc = 0.f;
        for (int o = lane; o < 100; o += 32) {
            float h = bsum[o];
            const float* wsr = Ws + o * 101;
            const float* wdr = Wd + o * 101;
            #pragma unroll 10
            for (int k = 0; k < 100; k++) {
                h = fmaf(wsr[k], zs[k], h);
                h = fmaf(wdr[k], zd[k], h);
            }
            h = fmaxf(h, 0.f);
            acc = fmaf(h, wf[o], acc);
        }
        #pragma unroll
        for (int o = 16; o; o >>= 1) acc += __shfl_xor_sync(0xffffffffu, acc, o);
        if (lane == 0) out[p] = acc + bf0;
        __syncwarp();
    }
}

// ---------------- launch ----------------------------------------------------------
extern "C" void kernel_launch(void* const* d_in, const int* in_sizes, int n_in,
                              void* d_out, int out_size)
{
    const float* z     = (const float*)d_in[0];
    const float* lu    = (const float*)d_in[1];
    const float* t     = (const float*)d_in[2];
    const float* msg   = (const float*)d_in[3];
    const float* tw    = (const float*)d_in[4];
    const float* tb    = (const float*)d_in[5];
    const float* Wq    = (const float*)d_in[6];
    const float* bq    = (const float*)d_in[7];
    const float* Wk    = (const float*)d_in[8];
    const float* bk    = (const float*)d_in[9];
    const float* Wv    = (const float*)d_in[10];
    const float* bv    = (const float*)d_in[11];
    const float* We    = (const float*)d_in[12];
    const float* Wskip = (const float*)d_in[13];
    const float* bskip = (const float*)d_in[14];
    const float* Wsrc  = (const float*)d_in[15];
    const float* bsrc  = (const float*)d_in[16];
    const float* Wdst  = (const float*)d_in[17];
    const float* bdst  = (const float*)d_in[18];
    const float* Wf    = (const float*)d_in[19];
    const float* bf    = (const float*)d_in[20];
    const int*   n_id  = (const int*)d_in[21];
    const int*   srcp  = (const int*)d_in[22];
    const int*   dstp  = (const int*)d_in[23];
    const int*   ei    = (const int*)d_in[24];

    int N = in_sizes[0] / 100;
    int E = in_sizes[2];
    int B = in_sizes[22];
    float* out = (float*)d_out;

    const int SMEM_QKVS  = (100 * GBM + 100 * 100 + 100) * 4;        // 91.6 KB
    const int SMEM_EPROJ = (101 * GBM + 101 * 100 + 200) * 4;        // 92.9 KB
    const int SMEM_LP    = (2 * 100 * 101 + 200 + 4 * 200) * 4;      // 84.8 KB

    cudaFuncSetAttribute(qkvs_kernel,    cudaFuncAttributeMaxDynamicSharedMemorySize, SMEM_QKVS);
    cudaFuncSetAttribute(eproj_kernel,   cudaFuncAttributeMaxDynamicSharedMemorySize, SMEM_EPROJ);
    cudaFuncSetAttribute(linkpred_kernel,cudaFuncAttributeMaxDynamicSharedMemorySize, SMEM_LP);

    init_kernel<<<(MAXNODES + 255) / 256, 256>>>(N);
    assoc_kernel<<<(N + 255) / 256, 256>>>(n_id, N);

    dim3 gq((N + GBM - 1) / GBM, 4);
    qkvs_kernel<<<gq, GTHREADS, SMEM_QKVS>>>(z, Wq, bq, Wk, bk, Wv, bv, Wskip, bskip, N);

    eproj_kernel<<<(E + GBM - 1) / GBM, GTHREADS, SMEM_EPROJ>>>(lu, t, msg, tw, tb, We, ei, E);

    alpha_kernel<<<(E + 7) / 8, 256>>>(ei, E);
    aexp_kernel<<<(2 * E + 255) / 256, 256>>>(ei, E);
    scatter_kernel<<<(E + 7) / 8, 256>>>(ei, E);

    linkpred_kernel<<<296, 128, SMEM_LP>>>(Wsrc, bsrc, Wdst, bdst, Wf, bf,
                                           srcp, dstp, out, B);
}

// round 4
// speedup vs baseline: 1.0126x; 1.0126x over previous
#include <cuda_runtime.h>
#include <math.h>

typedef unsigned long long ull;

// ---------------- static scratch (no runtime allocation allowed) ----------------
#define MAXN 100000
#define MAXE 500000
#define MAXNODES 1000000

__device__ int   g_assoc[MAXNODES];
__device__ float g_Q  [(size_t)MAXN*100];
__device__ float g_K  [(size_t)MAXN*100];
__device__ float g_V  [(size_t)MAXN*100];
__device__ float g_AGG[(size_t)MAXN*100];      // skip output, then scatter-accumulated
__device__ float g_EPROJ[(size_t)MAXE*100];
__device__ float g_alpha[(size_t)MAXE*2];
__device__ float g_aexp [(size_t)MAXE*2];
__device__ float g_amax [(size_t)MAXN*2];
__device__ float g_aden [(size_t)MAXN*2];

// ---------------- f32x2 packed-FMA helpers (full-rate FFMA on sm_103a) ----------
__device__ __forceinline__ ull pack2(float x, float y) {
    ull r; asm("mov.b64 %0,{%1,%2};" : "=l"(r) : "f"(x), "f"(y)); return r;
}
__device__ __forceinline__ float2 unpack2(ull v) {
    float2 r; asm("mov.b64 {%0,%1},%2;" : "=f"(r.x), "=f"(r.y) : "l"(v)); return r;
}
__device__ __forceinline__ void ffma2(ull& d, ull a, ull b) {
    asm("fma.rn.f32x2 %0,%1,%2,%3;" : "=l"(d) : "l"(a), "l"(b), "l"(d));
}

__device__ __forceinline__ void atomicMaxF(float* addr, float v) {
    if (v >= 0.f) atomicMax((int*)addr, __float_as_int(v));
    else          atomicMin((unsigned int*)addr, (unsigned int)__float_as_int(v));
}

// ---------------- init: assoc=0, amax=-inf, aden=0 ------------------------------
__global__ void init_kernel(int N) {
    int i = blockIdx.x * blockDim.x + threadIdx.x;
    if (i < MAXNODES) g_assoc[i] = 0;
    if (i < 2 * N) { g_amax[i] = -3.402823466e38f; g_aden[i] = 0.f; }
}

__global__ void assoc_kernel(const int* __restrict__ n_id, int N) {
    int i = blockIdx.x * blockDim.x + threadIdx.x;
    if (i < N) g_assoc[n_id[i]] = i;
}

// ---------------- fused Q/K/V/skip GEMM: C = z @ W^T + b -------------------------
// k-tiled A-panel (KT=50) so smem ~64.5KB -> 3 CTAs/SM.
#define GBM 128
#define GTHREADS 320
__global__ void __launch_bounds__(GTHREADS, 3) qkvs_kernel(
    const float* __restrict__ z,
    const float* __restrict__ W0, const float* __restrict__ b0,
    const float* __restrict__ W1, const float* __restrict__ b1,
    const float* __restrict__ W2, const float* __restrict__ b2,
    const float* __restrict__ W3, const float* __restrict__ b3,
    int N)
{
    extern __shared__ float sm[];
    float* a_s    = sm;                 // [50][128] k-major tile
    float* b_s    = sm + 50 * GBM;      // [100][100] k-major (W^T), full
    float* bias_s = b_s + 100 * 100;    // [100]

    const float* W; const float* bias; float* out;
    switch (blockIdx.y) {
        case 0:  W = W0; bias = b0; out = g_Q;   break;
        case 1:  W = W1; bias = b1; out = g_K;   break;
        case 2:  W = W2; bias = b2; out = g_V;   break;
        default: W = W3; bias = b3; out = g_AGG; break;
    }
    int tid  = threadIdx.x;
    int row0 = blockIdx.x * GBM;

    for (int idx = tid; idx < 10000; idx += GTHREADS) {
        int o = idx / 100, k = idx - o * 100;
        b_s[k * 100 + o] = W[idx];
    }
    if (tid < 100) bias_s[tid] = bias[tid];

    int cg = tid % 10, rg = tid / 10;
    int rb = rg * 4, cb = cg * 10;
    ull acc[4][5];
    #pragma unroll
    for (int i = 0; i < 4; i++)
        #pragma unroll
        for (int j = 0; j < 5; j++) acc[i][j] = 0ull;

    for (int kt = 0; kt < 2; kt++) {
        int k0 = kt * 50;
        __syncthreads();
        for (int idx = tid; idx < GBM * 50; idx += GTHREADS) {
            int r = idx / 50, kk = idx - r * 50;
            int gr = row0 + r;
            a_s[kk * GBM + r] = (gr < N) ? z[(size_t)gr * 100 + k0 + kk] : 0.f;
        }
        __syncthreads();

        const float* bp_base = b_s + (size_t)k0 * 100 + cb;
        #pragma unroll 2
        for (int kk = 0; kk < 50; kk++) {
            float4 av = *(const float4*)(a_s + kk * GBM + rb);
            ull a2[4] = { pack2(av.x, av.x), pack2(av.y, av.y),
                          pack2(av.z, av.z), pack2(av.w, av.w) };
            const ull* bp = (const ull*)(bp_base + kk * 100);
            ull b2[5];
            #pragma unroll
            for (int j = 0; j < 5; j++) b2[j] = bp[j];
            #pragma unroll
            for (int i = 0; i < 4; i++)
                #pragma unroll
                for (int j = 0; j < 5; j++) ffma2(acc[i][j], a2[i], b2[j]);
        }
    }

    #pragma unroll
    for (int i = 0; i < 4; i++) {
        int gr = row0 + rb + i;
        if (gr < N) {
            float2* op = (float2*)(out + (size_t)gr * 100 + cb);
            #pragma unroll
            for (int j = 0; j < 5; j++) {
                float2 r = unpack2(acc[i][j]);
                r.x += bias_s[cb + 2 * j];
                r.y += bias_s[cb + 2 * j + 1];
                op[j] = r;
            }
        }
    }
}

// ---------------- edge GEMM + fused alpha: e_proj = edge_attr @ We^T -------------
// edge_attr generated in smem per k-tile; alpha = q[dst].(k[src]+e_proj)/sqrt(50)
// computed in the epilogue (partial per colgroup, smem-atomic reduced).
__global__ void __launch_bounds__(GTHREADS, 3) eproj_kernel(
    const float* __restrict__ lu, const float* __restrict__ t,
    const float* __restrict__ msg,
    const float* __restrict__ tw, const float* __restrict__ tb,
    const float* __restrict__ We, const int* __restrict__ ei, int E)
{
    extern __shared__ float sm[];
    float* a_s   = sm;                    // [51][128] generated tile
    float* b_s   = sm + 51 * GBM;         // [101][100] k-major (We^T), full
    float* tw_s  = b_s + 101 * 100;       // [100]
    float* tb_s  = tw_s + 100;            // [100]
    float* rel_s = tb_s + 100;            // [128]
    float* msg_s = rel_s + GBM;           // [128]
    float* apart = msg_s + GBM;           // [128*2] alpha partials
    int*   sidx  = (int*)(apart + 2*GBM); // [128]
    int*   didx  = sidx + GBM;            // [128]

    int tid  = threadIdx.x;
    int row0 = blockIdx.x * GBM;

    if (tid < GBM) {
        int e = row0 + tid; float rv = 0.f, mv = 0.f; int s = 0, d = 0;
        if (e < E) { s = ei[e]; d = ei[E + e]; rv = lu[s] - t[e]; mv = msg[e]; }
        rel_s[tid] = rv; msg_s[tid] = mv; sidx[tid] = s; didx[tid] = d;
    }
    if (tid >= GBM && tid < GBM + 100) {
        int k = tid - GBM; tw_s[k] = tw[k]; tb_s[k] = tb[k];
    }
    if (tid < 2 * GBM) apart[tid] = 0.f;
    for (int idx = tid; idx < 10100; idx += GTHREADS) {
        int o = idx / 101, k = idx - o * 101;
        b_s[k * 100 + o] = We[idx];
    }

    int cg = tid % 10, rg = tid / 10;
    int rb = rg * 4, cb = cg * 10;
    ull acc[4][5];
    #pragma unroll
    for (int i = 0; i < 4; i++)
        #pragma unroll
        for (int j = 0; j < 5; j++) acc[i][j] = 0ull;

    // tiles: [0,51) and [51,101); k==100 row is msg
    #pragma unroll 1
    for (int kt = 0; kt < 2; kt++) {
        int k0 = (kt == 0) ? 0 : 51;
        int kn = (kt == 0) ? 51 : 50;
        __syncthreads();
        for (int idx = tid; idx < kn * GBM; idx += GTHREADS) {
            int kk = idx >> 7, r = idx & (GBM - 1);
            int k = k0 + kk;
            a_s[idx] = (k < 100) ? cosf(fmaf(rel_s[r], tw_s[k], tb_s[k]))
                                 : msg_s[r];
        }
        __syncthreads();

        const float* bp_base = b_s + (size_t)k0 * 100 + cb;
        #pragma unroll 2
        for (int kk = 0; kk < kn; kk++) {
            float4 av = *(const float4*)(a_s + kk * GBM + rb);
            ull a2[4] = { pack2(av.x, av.x), pack2(av.y, av.y),
                          pack2(av.z, av.z), pack2(av.w, av.w) };
            const ull* bp = (const ull*)(bp_base + kk * 100);
            ull b2[5];
            #pragma unroll
            for (int j = 0; j < 5; j++) b2[j] = bp[j];
            #pragma unroll
            for (int i = 0; i < 4; i++)
                #pragma unroll
                for (int j = 0; j < 5; j++) ffma2(acc[i][j], a2[i], b2[j]);
        }
    }

    // epilogue: store e_proj + alpha partial for this colgroup
    int h = (cb < 50) ? 0 : 1;
    #pragma unroll
    for (int i = 0; i < 4; i++) {
        int r = rb + i;
        int e = row0 + r;
        if (e < E) {
            int s = sidx[r], d = didx[r];
            const float2* qp = (const float2*)(g_Q + (size_t)d * 100 + cb);
            const float2* kp = (const float2*)(g_K + (size_t)s * 100 + cb);
            float2* op = (float2*)(g_EPROJ + (size_t)e * 100 + cb);
            float part = 0.f;
            #pragma unroll
            for (int j = 0; j < 5; j++) {
                float2 ep = unpack2(acc[i][j]);
                float2 qv = qp[j];
                float2 kv = kp[j];
                part = fmaf(qv.x, kv.x + ep.x, part);
                part = fmaf(qv.y, kv.y + ep.y, part);
                op[j] = ep;
            }
            atomicAdd(&apart[2 * r + h], part);
        }
    }
    __syncthreads();

    if (tid < 2 * GBM) {
        int r = tid >> 1, hh = tid & 1;
        int e = row0 + r;
        if (e < E) {
            const float inv = 0.14142135623730951f; // 1/sqrt(50)
            float a = apart[tid] * inv;
            g_alpha[2 * (size_t)e + hh] = a;
            atomicMaxF(&g_amax[2 * didx[r] + hh], a);
        }
    }
}

// ---------------- a = exp(alpha - amax[dst]); aden += a --------------------------
__global__ void aexp_kernel(const int* __restrict__ ei, int E)
{
    int i = blockIdx.x * blockDim.x + threadIdx.x;
    if (i >= 2 * E) return;
    int e = i >> 1, h = i & 1;
    int d = ei[E + e];
    float a = expf(g_alpha[i] - g_amax[2 * d + h]);
    g_aexp[i] = a;
    atomicAdd(&g_aden[2 * d + h], a);
}

// ---------------- agg[dst] += (v[src] + e_proj) * a/aden (float4 red) ------------
__global__ void scatter_kernel(const int* __restrict__ ei, int E)
{
    int gw   = (blockIdx.x * blockDim.x + threadIdx.x) >> 5;
    int lane = threadIdx.x & 31;
    if (gw >= E || lane >= 25) return;
    int s = ei[gw], d = ei[E + gw];
    float c0 = g_aexp[2 * gw]     / g_aden[2 * d];
    float c1 = g_aexp[2 * gw + 1] / g_aden[2 * d + 1];
    int col = lane * 4;
    float4 v4 = *(const float4*)(g_V + (size_t)s * 100 + col);
    float4 e4 = *(const float4*)(g_EPROJ + (size_t)gw * 100 + col);
    float4 r;
    r.x = (v4.x + e4.x) * ((col + 0) < 50 ? c0 : c1);
    r.y = (v4.y + e4.y) * ((col + 1) < 50 ? c0 : c1);
    r.z = (v4.z + e4.z) * ((col + 2) < 50 ? c0 : c1);
    r.w = (v4.w + e4.w) * ((col + 3) < 50 ? c0 : c1);
    atomicAdd((float4*)(g_AGG + (size_t)d * 100 + col), r);
}

// ---------------- link predictor -------------------------------------------------
__global__ void __launch_bounds__(128) linkpred_kernel(
    const float* __restrict__ Wsrc, const float* __restrict__ bsrc,
    const float* __restrict__ Wdst, const float* __restrict__ bdst,
    const float* __restrict__ Wf,   const float* __restrict__ bf,
    const int* __restrict__ src, const int* __restrict__ dst,
    float* __restrict__ out, int B)
{
    extern __shared__ float sm[];
    float* Ws   = sm;                 // [100][101] padded (conflict-free)
    float* Wd   = Ws + 100 * 101;
    float* bsum = Wd + 100 * 101;     // bsrc+bdst
    float* wf   = bsum + 100;
    float* zrow = wf + 100;           // 4 warps * 200

    int tid = threadIdx.x, lane = tid & 31, warp = tid >> 5;
    for (int idx = tid; idx < 10000; idx += 128) {
        int o = idx / 100, k = idx - o * 100;
        Ws[o * 101 + k] = Wsrc[idx];
        Wd[o * 101 + k] = Wdst[idx];
    }
    if (tid < 100) { bsum[tid] = bsrc[tid] + bdst[tid]; wf[tid] = Wf[tid]; }
    __syncthreads();

    float bf0 = bf[0];
    float* zs = zrow + warp * 200;
    float* zd = zs + 100;

    for (int p = blockIdx.x * 4 + warp; p < B; p += gridDim.x * 4) {
        int sp = g_assoc[src[p]];
        int dp = g_assoc[dst[p]];
        for (int c = lane; c < 100; c += 32) {
            zs[c] = g_AGG[(size_t)sp * 100 + c];
            zd[c] = g_AGG[(size_t)dp * 100 + c];
        }
        __syncwarp();
        float acc = 0.f;
        for (int o = lane; o < 100; o += 32) {
            float h = bsum[o];
            const float* wsr = Ws + o * 101;
            const float* wdr = Wd + o * 101;
            #pragma unroll 10
            for (int k = 0; k < 100; k++) {
                h = fmaf(wsr[k], zs[k], h);
                h = fmaf(wdr[k], zd[k], h);
            }
            h = fmaxf(h, 0.f);
            acc = fmaf(h, wf[o], acc);
        }
        #pragma unroll
        for (int o = 16; o; o >>= 1) acc += __shfl_xor_sync(0xffffffffu, acc, o);
        if (lane == 0) out[p] = acc + bf0;
        __syncwarp();
    }
}

// ---------------- launch ----------------------------------------------------------
extern "C" void kernel_launch(void* const* d_in, const int* in_sizes, int n_in,
                              void* d_out, int out_size)
{
    const float* z     = (const float*)d_in[0];
    const float* lu    = (const float*)d_in[1];
    const float* t     = (const float*)d_in[2];
    const float* msg   = (const float*)d_in[3];
    const float* tw    = (const float*)d_in[4];
    const float* tb    = (const float*)d_in[5];
    const float* Wq    = (const float*)d_in[6];
    const float* bq    = (const float*)d_in[7];
    const float* Wk    = (const float*)d_in[8];
    const float* bk    = (const float*)d_in[9];
    const float* Wv    = (const float*)d_in[10];
    const float* bv    = (const float*)d_in[11];
    const float* We    = (const float*)d_in[12];
    const float* Wskip = (const float*)d_in[13];
    const float* bskip = (const float*)d_in[14];
    const float* Wsrc  = (const float*)d_in[15];
    const float* bsrc  = (const float*)d_in[16];
    const float* Wdst  = (const float*)d_in[17];
    const float* bdst  = (const float*)d_in[18];
    const float* Wf    = (const float*)d_in[19];
    const float* bf    = (const float*)d_in[20];
    const int*   n_id  = (const int*)d_in[21];
    const int*   srcp  = (const int*)d_in[22];
    const int*   dstp  = (const int*)d_in[23];
    const int*   ei    = (const int*)d_in[24];

    int N = in_sizes[0] / 100;
    int E = in_sizes[2];
    int B = in_sizes[22];
    float* out = (float*)d_out;

    const int SMEM_QKVS  = (50 * GBM + 100 * 100 + 100) * 4;                       // ~64.5 KB
    const int SMEM_EPROJ = (51 * GBM + 101 * 100 + 200 + 4 * GBM) * 4 + 2*GBM*4;   // ~69 KB
    const int SMEM_LP    = (2 * 100 * 101 + 200 + 4 * 200) * 4;                    // ~84.8 KB

    cudaFuncSetAttribute(qkvs_kernel,    cudaFuncAttributeMaxDynamicSharedMemorySize, SMEM_QKVS);
    cudaFuncSetAttribute(eproj_kernel,   cudaFuncAttributeMaxDynamicSharedMemorySize, SMEM_EPROJ);
    cudaFuncSetAttribute(linkpred_kernel,cudaFuncAttributeMaxDynamicSharedMemorySize, SMEM_LP);

    init_kernel<<<(MAXNODES + 255) / 256, 256>>>(N);
    assoc_kernel<<<(N + 255) / 256, 256>>>(n_id, N);

    dim3 gq((N + GBM - 1) / GBM, 4);
    qkvs_kernel<<<gq, GTHREADS, SMEM_QKVS>>>(z, Wq, bq, Wk, bk, Wv, bv, Wskip, bskip, N);

    eproj_kernel<<<(E + GBM - 1) / GBM, GTHREADS, SMEM_EPROJ>>>(lu, t, msg, tw, tb, We, ei, E);

    aexp_kernel<<<(2 * E + 255) / 256, 256>>>(ei, E);
    scatter_kernel<<<(E + 7) / 8, 256>>>(ei, E);

    linkpred_kernel<<<296, 128, SMEM_LP>>>(Wsrc, bsrc, Wdst, bdst, Wf, bf,
                                           srcp, dstp, out, B);
}

// round 6
// speedup vs baseline: 1.0251x; 1.0123x over previous
#include <cuda_runtime.h>
#include <math.h>

typedef unsigned long long ull;

// ---------------- static scratch (no runtime allocation allowed) ----------------
#define MAXN 100000
#define MAXNODES 1000000

__device__ int   g_assoc[MAXNODES];
__device__ float g_Q   [(size_t)MAXN*100];
__device__ float g_K   [(size_t)MAXN*100];
__device__ float g_V   [(size_t)MAXN*100];
__device__ float g_AGG [(size_t)MAXN*100];   // skip projection (z @ Wskip^T + b)
__device__ float g_AGGW[(size_t)MAXN*100];   // unnormalized attention aggregation
__device__ float g_aden[(size_t)MAXN*2];     // softmax denominators per (node, head)

// ---------------- f32x2 packed-FMA helpers (full-rate FFMA on sm_103a) ----------
__device__ __forceinline__ ull pack2(float x, float y) {
    ull r; asm("mov.b64 %0,{%1,%2};" : "=l"(r) : "f"(x), "f"(y)); return r;
}
__device__ __forceinline__ float2 unpack2(ull v) {
    float2 r; asm("mov.b64 {%0,%1},%2;" : "=f"(r.x), "=f"(r.y) : "l"(v)); return r;
}
__device__ __forceinline__ void ffma2(ull& d, ull a, ull b) {
    asm("fma.rn.f32x2 %0,%1,%2,%3;" : "=l"(d) : "l"(a), "l"(b), "l"(d));
}

// ---------------- init: AGGW = 0, aden = 0 ---------------------------------------
__global__ void init_kernel(int N) {
    int i = blockIdx.x * blockDim.x + threadIdx.x;
    if (i < N * 25) ((float4*)g_AGGW)[i] = make_float4(0.f, 0.f, 0.f, 0.f);
    if (i < 2 * N) g_aden[i] = 0.f;
}

__global__ void assoc_kernel(const int* __restrict__ n_id, int N) {
    int i = blockIdx.x * blockDim.x + threadIdx.x;
    if (i < N) g_assoc[n_id[i]] = i;
}

// =================================================================================
// fused Q/K/V/skip GEMM: C = z @ W^T + b
// 160 threads: 32 rowgroups (TM=4) x 5 colgroups (TN=20 as 10 f32x2).
// persistent CTAs: weights staged once, row-tiles streamed.
// =================================================================================
#define TPB 160
#define ASTRIDE 53
__global__ void __launch_bounds__(TPB, 3) qkvs_kernel(
    const float* __restrict__ z,
    const float* __restrict__ W0, const float* __restrict__ b0,
    const float* __restrict__ W1, const float* __restrict__ b1,
    const float* __restrict__ W2, const float* __restrict__ b2v,
    const float* __restrict__ W3, const float* __restrict__ b3,
    int N, int ntiles)
{
    extern __shared__ float sm[];
    float* b_s    = sm;                  // [100][100] k-major (W^T)
    float* a_s    = sm + 10000;          // [128][53] row-major, padded
    float* bias_s = a_s + 128 * ASTRIDE; // [100]

    const float* W; const float* bias; float* out;
    switch (blockIdx.y) {
        case 0:  W = W0; bias = b0;  out = g_Q;   break;
        case 1:  W = W1; bias = b1;  out = g_K;   break;
        case 2:  W = W2; bias = b2v; out = g_V;   break;
        default: W = W3; bias = b3;  out = g_AGG; break;
    }
    int tid = threadIdx.x;

    for (int idx = tid; idx < 10000; idx += TPB) {
        int o = idx / 100, k = idx - o * 100;
        b_s[k * 100 + o] = W[idx];
    }
    if (tid < 100) bias_s[tid] = bias[tid];

    int cg = tid % 5, rg = tid / 5;
    int rb = rg * 4, cb = cg * 20;

    for (int tile = blockIdx.x; tile < ntiles; tile += gridDim.x) {
        int row0 = tile * 128;
        ull acc[4][10];
        #pragma unroll
        for (int i = 0; i < 4; i++)
            #pragma unroll
            for (int j = 0; j < 10; j++) acc[i][j] = 0ull;

        #pragma unroll 1
        for (int kt = 0; kt < 2; kt++) {
            int k0 = kt * 50;
            __syncthreads();
            for (int idx = tid; idx < 6400; idx += TPB) {
                int r = idx / 50, kk = idx - r * 50;
                int gr = row0 + r;
                a_s[r * ASTRIDE + kk] = (gr < N) ? z[(size_t)gr * 100 + k0 + kk] : 0.f;
            }
            __syncthreads();

            const float* bb = b_s + k0 * 100 + cb;
            const float* ab = a_s + rb * ASTRIDE;
            #pragma unroll 2
            for (int kk = 0; kk < 50; kk++) {
                float a0 = ab[kk];
                float a1 = ab[ASTRIDE + kk];
                float a2f = ab[2 * ASTRIDE + kk];
                float a3 = ab[3 * ASTRIDE + kk];
                ull a2[4] = { pack2(a0, a0), pack2(a1, a1),
                              pack2(a2f, a2f), pack2(a3, a3) };
                const ulonglong2* bp = (const ulonglong2*)(bb + kk * 100);
                ulonglong2 u0 = bp[0], u1 = bp[1], u2 = bp[2], u3 = bp[3], u4 = bp[4];
                ull b2[10] = { u0.x, u0.y, u1.x, u1.y, u2.x,
                               u2.y, u3.x, u3.y, u4.x, u4.y };
                #pragma unroll
                for (int i = 0; i < 4; i++)
                    #pragma unroll
                    for (int j = 0; j < 10; j++) ffma2(acc[i][j], a2[i], b2[j]);
            }
        }

        #pragma unroll
        for (int i = 0; i < 4; i++) {
            int gr = row0 + rb + i;
            if (gr < N) {
                float2* op = (float2*)(out + (size_t)gr * 100 + cb);
                #pragma unroll
                for (int j = 0; j < 10; j++) {
                    float2 r = unpack2(acc[i][j]);
                    r.x += bias_s[cb + 2 * j];
                    r.y += bias_s[cb + 2 * j + 1];
                    op[j] = r;
                }
            }
        }
    }
}

// =================================================================================
// fused edge kernel: e_proj GEMM (attr generated in smem) + alpha + max-free
// softmax weight + weighted scatter. No e_proj materialization.
// =================================================================================
__global__ void __launch_bounds__(TPB, 3) edge_kernel(
    const float* __restrict__ lu, const float* __restrict__ t,
    const float* __restrict__ msg,
    const float* __restrict__ tw, const float* __restrict__ tb,
    const float* __restrict__ We, const int* __restrict__ ei,
    int E, int ntiles)
{
    extern __shared__ float sm[];
    float* b_s   = sm;                      // [101][100] k-major (We^T)
    float* a_s   = b_s + 10100;             // [128][53] generated attr tile
    float* tw_s  = a_s + 128 * ASTRIDE;     // [100]
    float* tb_s  = tw_s + 100;              // [100]
    float* rel_s = tb_s + 100;              // [128]
    float* msg_s = rel_s + 128;             // [128]
    float* apart = msg_s + 128;             // [256] alpha partials, then w
    int*   sidx  = (int*)(apart + 256);     // [128]
    int*   didx  = sidx + 128;              // [128]

    int tid = threadIdx.x;
    for (int idx = tid; idx < 10100; idx += TPB) {
        int o = idx / 101, k = idx - o * 101;
        b_s[k * 100 + o] = We[idx];
    }
    if (tid < 100) { tw_s[tid] = tw[tid]; tb_s[tid] = tb[tid]; }

    int cg = tid % 5, rg = tid / 5;
    int rb = rg * 4, cb = cg * 20;
    const float inv = 0.14142135623730951f;   // 1/sqrt(50)

    for (int tile = blockIdx.x; tile < ntiles; tile += gridDim.x) {
        int e0 = tile * 128;
        __syncthreads();                       // prev tile fully consumed
        if (tid < 128) {
            int e = e0 + tid; float rv = 0.f, mv = 0.f; int s = 0, d = 0;
            if (e < E) { s = ei[e]; d = ei[E + e]; rv = lu[s] - t[e]; mv = msg[e]; }
            rel_s[tid] = rv; msg_s[tid] = mv; sidx[tid] = s; didx[tid] = d;
        }
        for (int idx = tid; idx < 256; idx += TPB) apart[idx] = 0.f;

        ull acc[4][10];
        #pragma unroll
        for (int i = 0; i < 4; i++)
            #pragma unroll
            for (int j = 0; j < 10; j++) acc[i][j] = 0ull;

        #pragma unroll 1
        for (int kt = 0; kt < 2; kt++) {
            int k0 = kt ? 51 : 0;
            int kn = kt ? 50 : 51;
            __syncthreads();
            for (int idx = tid; idx < kn * 128; idx += TPB) {
                int kk = idx >> 7, r = idx & 127;
                int k = k0 + kk;
                a_s[r * ASTRIDE + kk] =
                    (k < 100) ? cosf(fmaf(rel_s[r], tw_s[k], tb_s[k])) : msg_s[r];
            }
            __syncthreads();

            const float* bb = b_s + k0 * 100 + cb;
            const float* ab = a_s + rb * ASTRIDE;
            #pragma unroll 2
            for (int kk = 0; kk < kn; kk++) {
                float a0 = ab[kk];
                float a1 = ab[ASTRIDE + kk];
                float a2f = ab[2 * ASTRIDE + kk];
                float a3 = ab[3 * ASTRIDE + kk];
                ull a2[4] = { pack2(a0, a0), pack2(a1, a1),
                              pack2(a2f, a2f), pack2(a3, a3) };
                const ulonglong2* bp = (const ulonglong2*)(bb + kk * 100);
                ulonglong2 u0 = bp[0], u1 = bp[1], u2 = bp[2], u3 = bp[3], u4 = bp[4];
                ull b2[10] = { u0.x, u0.y, u1.x, u1.y, u2.x,
                               u2.y, u3.x, u3.y, u4.x, u4.y };
                #pragma unroll
                for (int i = 0; i < 4; i++)
                    #pragma unroll
                    for (int j = 0; j < 10; j++) ffma2(acc[i][j], a2[i], b2[j]);
            }
        }

        // ---- alpha partials: q[dst] . (k[src] + e_proj) over this colgroup ----
        #pragma unroll
        for (int i = 0; i < 4; i++) {
            int r = rb + i, e = e0 + r;
            if (e < E) {
                int s = sidx[r], d = didx[r];
                const float2* qp = (const float2*)(g_Q + (size_t)d * 100 + cb);
                const float2* kp = (const float2*)(g_K + (size_t)s * 100 + cb);
                float p0 = 0.f, p1 = 0.f;
                #pragma unroll
                for (int j = 0; j < 10; j++) {
                    float2 ep = unpack2(acc[i][j]);
                    float2 qv = qp[j];
                    float2 kv = kp[j];
                    float pj = qv.x * (kv.x + ep.x) + qv.y * (kv.y + ep.y);
                    if (cb + 2 * j < 50) p0 += pj; else p1 += pj;
                }
                if (cg < 3)  atomicAdd(&apart[2 * r],     p0);
                if (cg >= 2) atomicAdd(&apart[2 * r + 1], p1);
            }
        }
        __syncthreads();

        // ---- w = exp(alpha) (max-free), accumulate denominators ----
        for (int idx = tid; idx < 256; idx += TPB) {
            int r = idx >> 1, h = idx & 1;
            int e = e0 + r;
            if (e < E) {
                float w = expf(apart[idx] * inv);
                apart[idx] = w;                        // reuse as w_s
                atomicAdd(&g_aden[2 * didx[r] + h], w);
            }
        }
        __syncthreads();

        // ---- scatter: AGGW[dst] += (v[src] + e_proj) * w  (float4 REDs) ----
        #pragma unroll
        for (int i = 0; i < 4; i++) {
            int r = rb + i, e = e0 + r;
            if (e < E) {
                int s = sidx[r], d = didx[r];
                const float4* vp = (const float4*)(g_V + (size_t)s * 100 + cb);
                float w0 = apart[2 * r], w1 = apart[2 * r + 1];
                float4* op = (float4*)(g_AGGW + (size_t)d * 100 + cb);
                #pragma unroll
                for (int jj = 0; jj < 5; jj++) {
                    float4 vv = vp[jj];
                    float2 eA = unpack2(acc[i][2 * jj]);
                    float2 eB = unpack2(acc[i][2 * jj + 1]);
                    int c = cb + 4 * jj;
                    float wxy = (c < 50)     ? w0 : w1;
                    float wzw = (c + 2 < 50) ? w0 : w1;
                    float4 rr;
                    rr.x = (vv.x + eA.x) * wxy;
                    rr.y = (vv.y + eA.y) * wxy;
                    rr.z = (vv.z + eB.x) * wzw;
                    rr.w = (vv.w + eB.y) * wzw;
                    atomicAdd(op + jj, rr);
                }
            }
        }
    }
}

// =================================================================================
// link predictor with fused normalization:
// z_out = AGG(skip) + AGGW/aden ; out = relu(z_s@Ws^T + z_d@Wd^T + b) @ Wf^T + bf
// =================================================================================
__global__ void __launch_bounds__(128) linkpred_kernel(
    const float* __restrict__ Wsrc, const float* __restrict__ bsrc,
    const float* __restrict__ Wdst, const float* __restrict__ bdst,
    const float* __restrict__ Wf,   const float* __restrict__ bf,
    const int* __restrict__ src, const int* __restrict__ dst,
    float* __restrict__ out, int B)
{
    extern __shared__ float sm[];
    float* Ws   = sm;                 // [100][101] padded
    float* Wd   = Ws + 100 * 101;
    float* bsum = Wd + 100 * 101;
    float* wf   = bsum + 100;
    float* zrow = wf + 100;           // 4 warps * 200

    int tid = threadIdx.x, lane = tid & 31, warp = tid >> 5;
    for (int idx = tid; idx < 10000; idx += 128) {
        int o = idx / 100, k = idx - o * 100;
        Ws[o * 101 + k] = Wsrc[idx];
        Wd[o * 101 + k] = Wdst[idx];
    }
    if (tid < 100) { bsum[tid] = bsrc[tid] + bdst[tid]; wf[tid] = Wf[tid]; }
    __syncthreads();

    float bf0 = bf[0];
    float* zs = zrow + warp * 200;
    float* zd = zs + 100;

    for (int p = blockIdx.x * 4 + warp; p < B; p += gridDim.x * 4) {
        int sp = g_assoc[src[p]];
        int dp = g_assoc[dst[p]];
        float ds0 = g_aden[2 * sp], ds1 = g_aden[2 * sp + 1];
        float dd0 = g_aden[2 * dp], dd1 = g_aden[2 * dp + 1];
        float is0 = ds0 > 0.f ? 1.f / ds0 : 0.f;
        float is1 = ds1 > 0.f ? 1.f / ds1 : 0.f;
        float id0 = dd0 > 0.f ? 1.f / dd0 : 0.f;
        float id1 = dd1 > 0.f ? 1.f / dd1 : 0.f;
        for (int c = lane; c < 100; c += 32) {
            float invs = (c < 50) ? is0 : is1;
            float invd = (c < 50) ? id0 : id1;
            zs[c] = fmaf(g_AGGW[(size_t)sp * 100 + c], invs, g_AGG[(size_t)sp * 100 + c]);
            zd[c] = fmaf(g_AGGW[(size_t)dp * 100 + c], invd, g_AGG[(size_t)dp * 100 + c]);
        }
        __syncwarp();
        float acc = 0.f;
        for (int o = lane; o < 100; o += 32) {
            float h = bsum[o];
            const float* wsr = Ws + o * 101;
            const float* wdr = Wd + o * 101;
            #pragma unroll 10
            for (int k = 0; k < 100; k++) {
                h = fmaf(wsr[k], zs[k], h);
                h = fmaf(wdr[k], zd[k], h);
            }
            h = fmaxf(h, 0.f);
            acc = fmaf(h, wf[o], acc);
        }
        #pragma unroll
        for (int o = 16; o; o >>= 1) acc += __shfl_xor_sync(0xffffffffu, acc, o);
        if (lane == 0) out[p] = acc + bf0;
        __syncwarp();
    }
}

// ---------------- launch ----------------------------------------------------------
extern "C" void kernel_launch(void* const* d_in, const int* in_sizes, int n_in,
                              void* d_out, int out_size)
{
    const float* z     = (const float*)d_in[0];
    const float* lu    = (const float*)d_in[1];
    const float* t     = (const float*)d_in[2];
    const float* msg   = (const float*)d_in[3];
    const float* tw    = (const float*)d_in[4];
    const float* tb    = (const float*)d_in[5];
    const float* Wq    = (const float*)d_in[6];
    const float* bq    = (const float*)d_in[7];
    const float* Wk    = (const float*)d_in[8];
    const float* bk    = (const float*)d_in[9];
    const float* Wv    = (const float*)d_in[10];
    const float* bv    = (const float*)d_in[11];
    const float* We    = (const float*)d_in[12];
    const float* Wskip = (const float*)d_in[13];
    const float* bskip = (const float*)d_in[14];
    const float* Wsrc  = (const float*)d_in[15];
    const float* bsrc  = (const float*)d_in[16];
    const float* Wdst  = (const float*)d_in[17];
    const float* bdst  = (const float*)d_in[18];
    const float* Wf    = (const float*)d_in[19];
    const float* bf    = (const float*)d_in[20];
    const int*   n_id  = (const int*)d_in[21];
    const int*   srcp  = (const int*)d_in[22];
    const int*   dstp  = (const int*)d_in[23];
    const int*   ei    = (const int*)d_in[24];

    int N = in_sizes[0] / 100;
    int E = in_sizes[2];
    int B = in_sizes[22];
    float* out = (float*)d_out;

    int ntilesN = (N + 127) / 128;
    int ntilesE = (E + 127) / 128;

    const int SMEM_QKVS = (10000 + 128 * ASTRIDE + 100) * 4;                 // ~67.5 KB
    const int SMEM_EDGE = (10100 + 128 * ASTRIDE + 200 + 256 + 256) * 4
                        + 256 * 4;                                           // ~71.4 KB
    const int SMEM_LP   = (2 * 100 * 101 + 200 + 4 * 200) * 4;               // ~84.8 KB

    cudaFuncSetAttribute(qkvs_kernel,     cudaFuncAttributeMaxDynamicSharedMemorySize, SMEM_QKVS);
    cudaFuncSetAttribute(edge_kernel,     cudaFuncAttributeMaxDynamicSharedMemorySize, SMEM_EDGE);
    cudaFuncSetAttribute(linkpred_kernel, cudaFuncAttributeMaxDynamicSharedMemorySize, SMEM_LP);

    init_kernel<<<(N * 25 + 255) / 256, 256>>>(N);
    assoc_kernel<<<(N + 255) / 256, 256>>>(n_id, N);

    dim3 gq(111, 4);   // 444 persistent CTAs total (148 SMs x 3)
    qkvs_kernel<<<gq, TPB, SMEM_QKVS>>>(z, Wq, bq, Wk, bk, Wv, bv, Wskip, bskip,
                                        N, ntilesN);

    edge_kernel<<<444, TPB, SMEM_EDGE>>>(lu, t, msg, tw, tb, We, ei, E, ntilesE);

    linkpred_kernel<<<296, 128, SMEM_LP>>>(Wsrc, bsrc, Wdst, bdst, Wf, bf,
                                           srcp, dstp, out, B);
}

// round 7
// speedup vs baseline: 1.1316x; 1.1039x over previous
#include <cuda_runtime.h>
#include <math.h>

typedef unsigned long long ull;

// ---------------- static scratch (no runtime allocation allowed) ----------------
#define MAXN 100000
#define MAXNODES 1000000

__device__ int   g_assoc[MAXNODES];
__device__ float g_Q   [(size_t)MAXN*100];
__device__ float g_K   [(size_t)MAXN*100];
__device__ float g_V   [(size_t)MAXN*100];
__device__ float g_AGG [(size_t)MAXN*100];   // skip projection (z @ Wskip^T + b)
__device__ float g_AGGW[(size_t)MAXN*100];   // unnormalized attention aggregation
__device__ float g_aden[(size_t)MAXN*2];     // softmax denominators per (node, head)

// ---------------- f32x2 packed-FMA helpers (full-rate FFMA on sm_103a) ----------
__device__ __forceinline__ ull pack2(float x, float y) {
    ull r; asm("mov.b64 %0,{%1,%2};" : "=l"(r) : "f"(x), "f"(y)); return r;
}
__device__ __forceinline__ float2 unpack2(ull v) {
    float2 r; asm("mov.b64 {%0,%1},%2;" : "=f"(r.x), "=f"(r.y) : "l"(v)); return r;
}
__device__ __forceinline__ void ffma2(ull& d, ull a, ull b) {
    asm("fma.rn.f32x2 %0,%1,%2,%3;" : "=l"(d) : "l"(a), "l"(b), "l"(d));
}

// ---------------- init: AGGW = 0, aden = 0 ---------------------------------------
__global__ void init_kernel(int N) {
    int i = blockIdx.x * blockDim.x + threadIdx.x;
    if (i < N * 25) ((float4*)g_AGGW)[i] = make_float4(0.f, 0.f, 0.f, 0.f);
    if (i < 2 * N) g_aden[i] = 0.f;
}

__global__ void assoc_kernel(const int* __restrict__ n_id, int N) {
    int i = blockIdx.x * blockDim.x + threadIdx.x;
    if (i < N) g_assoc[n_id[i]] = i;
}

// =================================================================================
// fused Q/K/V/skip GEMM: C = z @ W^T + b
// 320 threads: 32 rowgroups (TM=4) x 10 colgroups (TN=10 as 5 f32x2).
// acc = 40 regs; 2-k-step inner loop; 2 CTAs/SM (reg cap ~96, no spills).
// =================================================================================
#define TPB 320
#define ASTRIDE 54
__global__ void __launch_bounds__(TPB, 2) qkvs_kernel(
    const float* __restrict__ z,
    const float* __restrict__ W0, const float* __restrict__ b0,
    const float* __restrict__ W1, const float* __restrict__ b1,
    const float* __restrict__ W2, const float* __restrict__ b2v,
    const float* __restrict__ W3, const float* __restrict__ b3,
    int N, int ntiles)
{
    extern __shared__ float sm[];
    float* b_s    = sm;                  // [100][100] k-major (W^T)
    float* a_s    = sm + 10000;          // [128][54] row-major, padded even
    float* bias_s = a_s + 128 * ASTRIDE; // [100]

    const float* W; const float* bias; float* out;
    switch (blockIdx.y) {
        case 0:  W = W0; bias = b0;  out = g_Q;   break;
        case 1:  W = W1; bias = b1;  out = g_K;   break;
        case 2:  W = W2; bias = b2v; out = g_V;   break;
        default: W = W3; bias = b3;  out = g_AGG; break;
    }
    int tid = threadIdx.x;

    for (int idx = tid; idx < 10000; idx += TPB) {
        int o = idx / 100, k = idx - o * 100;
        b_s[k * 100 + o] = W[idx];
    }
    if (tid < 100) bias_s[tid] = bias[tid];

    int cg = tid % 10, rg = tid / 10;
    int rb = rg * 4, cb = cg * 10;
    const float* ab = a_s + rb * ASTRIDE;
    const float* bb = b_s + cb;

    for (int tile = blockIdx.x; tile < ntiles; tile += gridDim.x) {
        int row0 = tile * 128;
        ull acc[4][5];
        #pragma unroll
        for (int i = 0; i < 4; i++)
            #pragma unroll
            for (int j = 0; j < 5; j++) acc[i][j] = 0ull;

        #pragma unroll 1
        for (int kt = 0; kt < 2; kt++) {
            int k0 = kt * 50;
            __syncthreads();
            for (int idx = tid; idx < 6400; idx += TPB) {
                int r = idx / 50, kk = idx - r * 50;
                int gr = row0 + r;
                a_s[r * ASTRIDE + kk] = (gr < N) ? z[(size_t)gr * 100 + k0 + kk] : 0.f;
            }
            __syncthreads();

            #pragma unroll 2
            for (int kk2 = 0; kk2 < 25; kk2++) {
                int k = 2 * kk2;
                float2 av[4];
                #pragma unroll
                for (int i = 0; i < 4; i++)
                    av[i] = *(const float2*)(ab + i * ASTRIDE + k);
                const ull* bpa = (const ull*)(bb + (k0 + k) * 100);
                const ull* bpb = (const ull*)(bb + (k0 + k + 1) * 100);
                ull b2a[5], b2b[5];
                #pragma unroll
                for (int j = 0; j < 5; j++) { b2a[j] = bpa[j]; b2b[j] = bpb[j]; }
                #pragma unroll
                for (int i = 0; i < 4; i++) {
                    ull a2 = pack2(av[i].x, av[i].x);
                    #pragma unroll
                    for (int j = 0; j < 5; j++) ffma2(acc[i][j], a2, b2a[j]);
                }
                #pragma unroll
                for (int i = 0; i < 4; i++) {
                    ull a2 = pack2(av[i].y, av[i].y);
                    #pragma unroll
                    for (int j = 0; j < 5; j++) ffma2(acc[i][j], a2, b2b[j]);
                }
            }
        }

        #pragma unroll
        for (int i = 0; i < 4; i++) {
            int gr = row0 + rb + i;
            if (gr < N) {
                float2* op = (float2*)(out + (size_t)gr * 100 + cb);
                #pragma unroll
                for (int j = 0; j < 5; j++) {
                    float2 r = unpack2(acc[i][j]);
                    r.x += bias_s[cb + 2 * j];
                    r.y += bias_s[cb + 2 * j + 1];
                    op[j] = r;
                }
            }
        }
    }
}

// =================================================================================
// fused edge kernel: e_proj GEMM (attr generated in smem) + alpha + max-free
// softmax weight + weighted scatter. No e_proj materialization.
// =================================================================================
__global__ void __launch_bounds__(TPB, 2) edge_kernel(
    const float* __restrict__ lu, const float* __restrict__ t,
    const float* __restrict__ msg,
    const float* __restrict__ tw, const float* __restrict__ tb,
    const float* __restrict__ We, const int* __restrict__ ei,
    int E, int ntiles)
{
    extern __shared__ float sm[];
    float* b_s   = sm;                      // [101][100] k-major (We^T)
    float* a_s   = b_s + 10100;             // [128][54] generated attr tile
    float* tw_s  = a_s + 128 * ASTRIDE;     // [100]
    float* tb_s  = tw_s + 100;              // [100]
    float* rel_s = tb_s + 100;              // [128]
    float* msg_s = rel_s + 128;             // [128]
    float* apart = msg_s + 128;             // [256] alpha partials, then w
    int*   sidx  = (int*)(apart + 256);     // [128]
    int*   didx  = sidx + 128;              // [128]

    int tid = threadIdx.x;
    for (int idx = tid; idx < 10100; idx += TPB) {
        int o = idx / 101, k = idx - o * 101;
        b_s[k * 100 + o] = We[idx];
    }
    if (tid < 100) { tw_s[tid] = tw[tid]; tb_s[tid] = tb[tid]; }

    int cg = tid % 10, rg = tid / 10;
    int rb = rg * 4, cb = cg * 10;
    int h  = (cg >= 5) ? 1 : 0;             // head of this colgroup (TN=10 never spans)
    const float* ab = a_s + rb * ASTRIDE;
    const float* bb = b_s + cb;
    const float inv = 0.14142135623730951f; // 1/sqrt(50)

    for (int tile = blockIdx.x; tile < ntiles; tile += gridDim.x) {
        int e0 = tile * 128;
        __syncthreads();                     // prev tile fully consumed
        if (tid < 128) {
            int e = e0 + tid; float rv = 0.f, mv = 0.f; int s = 0, d = 0;
            if (e < E) { s = ei[e]; d = ei[E + e]; rv = lu[s] - t[e]; mv = msg[e]; }
            rel_s[tid] = rv; msg_s[tid] = mv; sidx[tid] = s; didx[tid] = d;
        }
        for (int idx = tid; idx < 256; idx += TPB) apart[idx] = 0.f;

        ull acc[4][5];
        #pragma unroll
        for (int i = 0; i < 4; i++)
            #pragma unroll
            for (int j = 0; j < 5; j++) acc[i][j] = 0ull;

        // k-tiles: [0,50) and [50,101); global k==100 row is msg
        #pragma unroll 1
        for (int kt = 0; kt < 2; kt++) {
            int k0 = kt ? 50 : 0;
            int kn = kt ? 51 : 50;
            __syncthreads();
            for (int idx = tid; idx < kn * 128; idx += TPB) {
                int r = idx / kn, kk = idx - r * kn;
                int k = k0 + kk;
                a_s[r * ASTRIDE + kk] =
                    (k < 100) ? cosf(fmaf(rel_s[r], tw_s[k], tb_s[k])) : msg_s[r];
            }
            __syncthreads();

            #pragma unroll 2
            for (int kk2 = 0; kk2 < 25; kk2++) {
                int k = 2 * kk2;
                float2 av[4];
                #pragma unroll
                for (int i = 0; i < 4; i++)
                    av[i] = *(const float2*)(ab + i * ASTRIDE + k);
                const ull* bpa = (const ull*)(bb + (k0 + k) * 100);
                const ull* bpb = (const ull*)(bb + (k0 + k + 1) * 100);
                ull b2a[5], b2b[5];
                #pragma unroll
                for (int j = 0; j < 5; j++) { b2a[j] = bpa[j]; b2b[j] = bpb[j]; }
                #pragma unroll
                for (int i = 0; i < 4; i++) {
                    ull a2 = pack2(av[i].x, av[i].x);
                    #pragma unroll
                    for (int j = 0; j < 5; j++) ffma2(acc[i][j], a2, b2a[j]);
                }
                #pragma unroll
                for (int i = 0; i < 4; i++) {
                    ull a2 = pack2(av[i].y, av[i].y);
                    #pragma unroll
                    for (int j = 0; j < 5; j++) ffma2(acc[i][j], a2, b2b[j]);
                }
            }
            if (kn & 1) {   // tail k-step (global k = 100, the msg row)
                const ull* bps = (const ull*)(bb + 100 * 100);
                ull b2s[5];
                #pragma unroll
                for (int j = 0; j < 5; j++) b2s[j] = bps[j];
                #pragma unroll
                for (int i = 0; i < 4; i++) {
                    float a1 = ab[i * ASTRIDE + 50];
                    ull a2 = pack2(a1, a1);
                    #pragma unroll
                    for (int j = 0; j < 5; j++) ffma2(acc[i][j], a2, b2s[j]);
                }
            }
        }

        // ---- alpha partials: q[dst] . (k[src] + e_proj) over this colgroup ----
        #pragma unroll
        for (int i = 0; i < 4; i++) {
            int r = rb + i, e = e0 + r;
            if (e < E) {
                int s = sidx[r], d = didx[r];
                const float2* qp = (const float2*)(g_Q + (size_t)d * 100 + cb);
                const float2* kp = (const float2*)(g_K + (size_t)s * 100 + cb);
                float part = 0.f;
                #pragma unroll
                for (int j = 0; j < 5; j++) {
                    float2 ep = unpack2(acc[i][j]);
                    float2 qv = qp[j];
                    float2 kv = kp[j];
                    part = fmaf(qv.x, kv.x + ep.x, part);
                    part = fmaf(qv.y, kv.y + ep.y, part);
                }
                atomicAdd(&apart[2 * r + h], part);
            }
        }
        __syncthreads();

        // ---- w = exp(alpha) (max-free), accumulate denominators ----
        for (int idx = tid; idx < 256; idx += TPB) {
            int r = idx >> 1, hh = idx & 1;
            int e = e0 + r;
            if (e < E) {
                float w = expf(apart[idx] * inv);
                apart[idx] = w;                        // reuse as w_s
                atomicAdd(&g_aden[2 * didx[r] + hh], w);
            }
        }
        __syncthreads();

        // ---- scatter: AGGW[dst] += (v[src] + e_proj) * w  (vector REDs) ----
        #pragma unroll
        for (int i = 0; i < 4; i++) {
            int r = rb + i, e = e0 + r;
            if (e < E) {
                int s = sidx[r], d = didx[r];
                const float2* vp = (const float2*)(g_V + (size_t)s * 100 + cb);
                float w = apart[2 * r + h];
                float m[10];
                #pragma unroll
                for (int j = 0; j < 5; j++) {
                    float2 ep = unpack2(acc[i][j]);
                    float2 vv = vp[j];
                    m[2 * j]     = (vv.x + ep.x) * w;
                    m[2 * j + 1] = (vv.y + ep.y) * w;
                }
                float* op = g_AGGW + (size_t)d * 100 + cb;
                if ((cg & 1) == 0) {   // cb % 4 == 0 : 4+4+2
                    atomicAdd((float4*)op,       make_float4(m[0], m[1], m[2], m[3]));
                    atomicAdd((float4*)(op + 4), make_float4(m[4], m[5], m[6], m[7]));
                    atomicAdd((float2*)(op + 8), make_float2(m[8], m[9]));
                } else {               // cb % 4 == 2 : 2+4+4
                    atomicAdd((float2*)op,       make_float2(m[0], m[1]));
                    atomicAdd((float4*)(op + 2), make_float4(m[2], m[3], m[4], m[5]));
                    atomicAdd((float4*)(op + 6), make_float4(m[6], m[7], m[8], m[9]));
                }
            }
        }
    }
}

// =================================================================================
// link predictor with fused normalization:
// z_out = AGG(skip) + AGGW/aden ; out = relu(z_s@Ws^T + z_d@Wd^T + b) @ Wf^T + bf
// =================================================================================
__global__ void __launch_bounds__(128) linkpred_kernel(
    const float* __restrict__ Wsrc, const float* __restrict__ bsrc,
    const float* __restrict__ Wdst, const float* __restrict__ bdst,
    const float* __restrict__ Wf,   const float* __restrict__ bf,
    const int* __restrict__ src, const int* __restrict__ dst,
    float* __restrict__ out, int B)
{
    extern __shared__ float sm[];
    float* Ws   = sm;                 // [100][101] padded
    float* Wd   = Ws + 100 * 101;
    float* bsum = Wd + 100 * 101;
    float* wf   = bsum + 100;
    float* zrow = wf + 100;           // 4 warps * 200

    int tid = threadIdx.x, lane = tid & 31, warp = tid >> 5;
    for (int idx = tid; idx < 10000; idx += 128) {
        int o = idx / 100, k = idx - o * 100;
        Ws[o * 101 + k] = Wsrc[idx];
        Wd[o * 101 + k] = Wdst[idx];
    }
    if (tid < 100) { bsum[tid] = bsrc[tid] + bdst[tid]; wf[tid] = Wf[tid]; }
    __syncthreads();

    float bf0 = bf[0];
    float* zs = zrow + warp * 200;
    float* zd = zs + 100;

    for (int p = blockIdx.x * 4 + warp; p < B; p += gridDim.x * 4) {
        int sp = g_assoc[src[p]];
        int dp = g_assoc[dst[p]];
        float ds0 = g_aden[2 * sp], ds1 = g_aden[2 * sp + 1];
        float dd0 = g_aden[2 * dp], dd1 = g_aden[2 * dp + 1];
        float is0 = ds0 > 0.f ? 1.f / ds0 : 0.f;
        float is1 = ds1 > 0.f ? 1.f / ds1 : 0.f;
        float id0 = dd0 > 0.f ? 1.f / dd0 : 0.f;
        float id1 = dd1 > 0.f ? 1.f / dd1 : 0.f;
        for (int c = lane; c < 100; c += 32) {
            float invs = (c < 50) ? is0 : is1;
            float invd = (c < 50) ? id0 : id1;
            zs[c] = fmaf(g_AGGW[(size_t)sp * 100 + c], invs, g_AGG[(size_t)sp * 100 + c]);
            zd[c] = fmaf(g_AGGW[(size_t)dp * 100 + c], invd, g_AGG[(size_t)dp * 100 + c]);
        }
        __syncwarp();
        float acc = 0.f;
        for (int o = lane; o < 100; o += 32) {
            float hh = bsum[o];
            const float* wsr = Ws + o * 101;
            const float* wdr = Wd + o * 101;
            #pragma unroll 10
            for (int k = 0; k < 100; k++) {
                hh = fmaf(wsr[k], zs[k], hh);
                hh = fmaf(wdr[k], zd[k], hh);
            }
            hh = fmaxf(hh, 0.f);
            acc = fmaf(hh, wf[o], acc);
        }
        #pragma unroll
        for (int o = 16; o; o >>= 1) acc += __shfl_xor_sync(0xffffffffu, acc, o);
        if (lane == 0) out[p] = acc + bf0;
        __syncwarp();
    }
}

// ---------------- launch ----------------------------------------------------------
extern "C" void kernel_launch(void* const* d_in, const int* in_sizes, int n_in,
                              void* d_out, int out_size)
{
    const float* z     = (const float*)d_in[0];
    const float* lu    = (const float*)d_in[1];
    const float* t     = (const float*)d_in[2];
    const float* msg   = (const float*)d_in[3];
    const float* tw    = (const float*)d_in[4];
    const float* tb    = (const float*)d_in[5];
    const float* Wq    = (const float*)d_in[6];
    const float* bq    = (const float*)d_in[7];
    const float* Wk    = (const float*)d_in[8];
    const float* bk    = (const float*)d_in[9];
    const float* Wv    = (const float*)d_in[10];
    const float* bv    = (const float*)d_in[11];
    const float* We    = (const float*)d_in[12];
    const float* Wskip = (const float*)d_in[13];
    const float* bskip = (const float*)d_in[14];
    const float* Wsrc  = (const float*)d_in[15];
    const float* bsrc  = (const float*)d_in[16];
    const float* Wdst  = (const float*)d_in[17];
    const float* bdst  = (const float*)d_in[18];
    const float* Wf    = (const float*)d_in[19];
    const float* bf    = (const float*)d_in[20];
    const int*   n_id  = (const int*)d_in[21];
    const int*   srcp  = (const int*)d_in[22];
    const int*   dstp  = (const int*)d_in[23];
    const int*   ei    = (const int*)d_in[24];

    int N = in_sizes[0] / 100;
    int E = in_sizes[2];
    int B = in_sizes[22];
    float* out = (float*)d_out;

    int ntilesN = (N + 127) / 128;
    int ntilesE = (E + 127) / 128;

    const int SMEM_QKVS = (10000 + 128 * ASTRIDE + 100) * 4;                  // ~68 KB
    const int SMEM_EDGE = (10100 + 128 * ASTRIDE + 200 + 256 + 256 + 256) * 4; // ~72 KB
    const int SMEM_LP   = (2 * 100 * 101 + 200 + 4 * 200) * 4;                // ~84.8 KB

    cudaFuncSetAttribute(qkvs_kernel,     cudaFuncAttributeMaxDynamicSharedMemorySize, SMEM_QKVS);
    cudaFuncSetAttribute(edge_kernel,     cudaFuncAttributeMaxDynamicSharedMemorySize, SMEM_EDGE);
    cudaFuncSetAttribute(linkpred_kernel, cudaFuncAttributeMaxDynamicSharedMemorySize, SMEM_LP);

    init_kernel<<<(N * 25 + 255) / 256, 256>>>(N);
    assoc_kernel<<<(N + 255) / 256, 256>>>(n_id, N);

    dim3 gq(74, 4);    // 296 persistent CTAs (148 SMs x 2)
    qkvs_kernel<<<gq, TPB, SMEM_QKVS>>>(z, Wq, bq, Wk, bk, Wv, bv, Wskip, bskip,
                                        N, ntilesN);

    edge_kernel<<<296, TPB, SMEM_EDGE>>>(lu, t, msg, tw, tb, We, ei, E, ntilesE);

    linkpred_kernel<<<296, 128, SMEM_LP>>>(Wsrc, bsrc, Wdst, bdst, Wf, bf,
                                           srcp, dstp, out, B);
}

// round 8
// speedup vs baseline: 1.2821x; 1.1330x over previous
#include <cuda_runtime.h>
#include <math.h>

typedef unsigned long long ull;

// ---------------- static scratch (no runtime allocation allowed) ----------------
#define MAXN 100000
#define MAXNODES 1000000

__device__ int   g_assoc[MAXNODES];
__device__ float g_Q   [(size_t)MAXN*100];
__device__ float g_K   [(size_t)MAXN*100];
__device__ float g_V   [(size_t)MAXN*100];
__device__ float g_AGG [(size_t)MAXN*100];   // skip projection (z @ Wskip^T + b)
__device__ float g_AGGW[(size_t)MAXN*100];   // unnormalized attention aggregation
__device__ float g_aden[(size_t)MAXN*2];     // softmax denominators per (node, head)

// ---------------- f32x2 packed-FMA helpers (full-rate FFMA on sm_103a) ----------
__device__ __forceinline__ ull pack2(float x, float y) {
    ull r; asm("mov.b64 %0,{%1,%2};" : "=l"(r) : "f"(x), "f"(y)); return r;
}
__device__ __forceinline__ float2 unpack2(ull v) {
    float2 r; asm("mov.b64 {%0,%1},%2;" : "=f"(r.x), "=f"(r.y) : "l"(v)); return r;
}
__device__ __forceinline__ void ffma2(ull& d, ull a, ull b) {
    asm("fma.rn.f32x2 %0,%1,%2,%3;" : "=l"(d) : "l"(a), "l"(b), "l"(d));
}

// ---------------- init: AGGW = 0, aden = 0 ---------------------------------------
__global__ void init_kernel(int N) {
    int i = blockIdx.x * blockDim.x + threadIdx.x;
    if (i < N * 25) ((float4*)g_AGGW)[i] = make_float4(0.f, 0.f, 0.f, 0.f);
    if (i < 2 * N) g_aden[i] = 0.f;
}

__global__ void assoc_kernel(const int* __restrict__ n_id, int N) {
    int i = blockIdx.x * blockDim.x + threadIdx.x;
    if (i < N) g_assoc[n_id[i]] = i;
}

// =================================================================================
// GEMM tile geometry: BM=128, BN=100, 160 threads = 16 rowgroups(TM=8) x 10 cg(TN=10)
// A panel k-major in smem: a_s[k*SA + r], SA=132 (16B-aligned rows, conflict-safe)
// =================================================================================
#define TPB 160
#define SA  132

// ---------------- fused Q/K/V/skip GEMM: C = z @ W^T + b -------------------------
__global__ void __launch_bounds__(TPB, 3) qkvs_kernel(
    const float* __restrict__ z,
    const float* __restrict__ W0, const float* __restrict__ b0,
    const float* __restrict__ W1, const float* __restrict__ b1,
    const float* __restrict__ W2, const float* __restrict__ b2v,
    const float* __restrict__ W3, const float* __restrict__ b3,
    int N, int ntiles)
{
    extern __shared__ float sm[];
    float* b_s    = sm;                  // [100][100] k-major (W^T)
    float* a_s    = sm + 10000;          // [50][132] k-major tile
    float* bias_s = a_s + 50 * SA;       // [100]

    const float* W; const float* bias; float* out;
    switch (blockIdx.y) {
        case 0:  W = W0; bias = b0;  out = g_Q;   break;
        case 1:  W = W1; bias = b1;  out = g_K;   break;
        case 2:  W = W2; bias = b2v; out = g_V;   break;
        default: W = W3; bias = b3;  out = g_AGG; break;
    }
    int tid = threadIdx.x;

    for (int idx = tid; idx < 10000; idx += TPB) {
        int o = idx / 100, k = idx - o * 100;
        b_s[k * 100 + o] = W[idx];
    }
    if (tid < 100) bias_s[tid] = bias[tid];

    int cg = tid % 10, rg = tid / 10;
    int rb = rg * 8, cb = cg * 10;
    const float* bb = b_s + cb;

    for (int tile = blockIdx.x; tile < ntiles; tile += gridDim.x) {
        int row0 = tile * 128;
        ull acc[8][5];
        #pragma unroll
        for (int i = 0; i < 8; i++)
            #pragma unroll
            for (int j = 0; j < 5; j++) acc[i][j] = 0ull;

        #pragma unroll 1
        for (int kt = 0; kt < 2; kt++) {
            int k0 = kt * 50;
            __syncthreads();
            // coalesced LDG (float2 along k), transposed STS into k-major a_s
            for (int idx = tid; idx < 3200; idx += TPB) {
                int r = idx / 25, kk2 = idx - r * 25;
                int gr = row0 + r;
                float2 v = make_float2(0.f, 0.f);
                if (gr < N) v = *(const float2*)(z + (size_t)gr * 100 + k0 + 2 * kk2);
                a_s[(2 * kk2) * SA + r]     = v.x;
                a_s[(2 * kk2 + 1) * SA + r] = v.y;
            }
            __syncthreads();

            #pragma unroll 2
            for (int kk = 0; kk < 50; kk++) {
                float4 a0 = *(const float4*)(a_s + kk * SA + rb);
                float4 a1 = *(const float4*)(a_s + kk * SA + rb + 4);
                const ull* bp = (const ull*)(bb + (k0 + kk) * 100);
                ull b2[5];
                #pragma unroll
                for (int j = 0; j < 5; j++) b2[j] = bp[j];
                ull av[8] = { pack2(a0.x, a0.x), pack2(a0.y, a0.y),
                              pack2(a0.z, a0.z), pack2(a0.w, a0.w),
                              pack2(a1.x, a1.x), pack2(a1.y, a1.y),
                              pack2(a1.z, a1.z), pack2(a1.w, a1.w) };
                #pragma unroll
                for (int i = 0; i < 8; i++)
                    #pragma unroll
                    for (int j = 0; j < 5; j++) ffma2(acc[i][j], av[i], b2[j]);
            }
        }

        #pragma unroll
        for (int i = 0; i < 8; i++) {
            int gr = row0 + rb + i;
            if (gr < N) {
                float2* op = (float2*)(out + (size_t)gr * 100 + cb);
                #pragma unroll
                for (int j = 0; j < 5; j++) {
                    float2 r = unpack2(acc[i][j]);
                    r.x += bias_s[cb + 2 * j];
                    r.y += bias_s[cb + 2 * j + 1];
                    op[j] = r;
                }
            }
        }
    }
}

// =================================================================================
// fused edge kernel: e_proj GEMM (attr generated in smem via __cosf) + alpha +
// max-free softmax weight + weighted scatter. No e_proj materialization.
// =================================================================================
__global__ void __launch_bounds__(TPB, 3) edge_kernel(
    const float* __restrict__ lu, const float* __restrict__ t,
    const float* __restrict__ msg,
    const float* __restrict__ tw, const float* __restrict__ tb,
    const float* __restrict__ We, const int* __restrict__ ei,
    int E, int ntiles)
{
    extern __shared__ float sm[];
    float* b_s   = sm;                      // [101][100] k-major (We^T)
    float* a_s   = b_s + 10100;             // [51][132] generated attr tile (k-major)
    float* tw_s  = a_s + 51 * SA;           // [100]
    float* tb_s  = tw_s + 100;              // [100]
    float* rel_s = tb_s + 100;              // [128]
    float* msg_s = rel_s + 128;             // [128]
    float* apart = msg_s + 128;             // [256] alpha partials, then w
    int*   sidx  = (int*)(apart + 256);     // [128]
    int*   didx  = sidx + 128;              // [128]

    int tid = threadIdx.x;
    for (int idx = tid; idx < 10100; idx += TPB) {
        int o = idx / 101, k = idx - o * 101;
        b_s[k * 100 + o] = We[idx];
    }
    if (tid < 100) { tw_s[tid] = tw[tid]; tb_s[tid] = tb[tid]; }

    int cg = tid % 10, rg = tid / 10;
    int rb = rg * 8, cb = cg * 10;
    int h  = (cg >= 5) ? 1 : 0;             // head of this colgroup (TN=10 never spans)
    const float* bb = b_s + cb;
    const float inv = 0.14142135623730951f; // 1/sqrt(50)

    for (int tile = blockIdx.x; tile < ntiles; tile += gridDim.x) {
        int e0 = tile * 128;
        __syncthreads();                     // prev tile fully consumed
        if (tid < 128) {
            int e = e0 + tid; float rv = 0.f, mv = 0.f; int s = 0, d = 0;
            if (e < E) { s = ei[e]; d = ei[E + e]; rv = lu[s] - t[e]; mv = msg[e]; }
            rel_s[tid] = rv; msg_s[tid] = mv; sidx[tid] = s; didx[tid] = d;
        }
        for (int idx = tid; idx < 256; idx += TPB) apart[idx] = 0.f;

        ull acc[8][5];
        #pragma unroll
        for (int i = 0; i < 8; i++)
            #pragma unroll
            for (int j = 0; j < 5; j++) acc[i][j] = 0ull;

        // k-tiles: [0,50) and [50,101); global k==100 row is msg
        #pragma unroll 1
        for (int kt = 0; kt < 2; kt++) {
            int k0 = kt ? 50 : 0;
            int kn = kt ? 51 : 50;
            __syncthreads();
            for (int idx = tid; idx < kn * 128; idx += TPB) {
                int r = idx & 127, kk = idx >> 7;
                int gk = k0 + kk;
                a_s[kk * SA + r] =
                    (gk < 100) ? __cosf(fmaf(rel_s[r], tw_s[gk], tb_s[gk])) : msg_s[r];
            }
            __syncthreads();

            #pragma unroll 2
            for (int kk = 0; kk < kn; kk++) {
                float4 a0 = *(const float4*)(a_s + kk * SA + rb);
                float4 a1 = *(const float4*)(a_s + kk * SA + rb + 4);
                const ull* bp = (const ull*)(bb + (k0 + kk) * 100);
                ull b2[5];
                #pragma unroll
                for (int j = 0; j < 5; j++) b2[j] = bp[j];
                ull av[8] = { pack2(a0.x, a0.x), pack2(a0.y, a0.y),
                              pack2(a0.z, a0.z), pack2(a0.w, a0.w),
                              pack2(a1.x, a1.x), pack2(a1.y, a1.y),
                              pack2(a1.z, a1.z), pack2(a1.w, a1.w) };
                #pragma unroll
                for (int i = 0; i < 8; i++)
                    #pragma unroll
                    for (int j = 0; j < 5; j++) ffma2(acc[i][j], av[i], b2[j]);
            }
        }

        // ---- alpha partials: q[dst] . (k[src] + e_proj) over this colgroup ----
        #pragma unroll
        for (int i = 0; i < 8; i++) {
            int r = rb + i, e = e0 + r;
            if (e < E) {
                int s = sidx[r], d = didx[r];
                const float2* qp = (const float2*)(g_Q + (size_t)d * 100 + cb);
                const float2* kp = (const float2*)(g_K + (size_t)s * 100 + cb);
                float part = 0.f;
                #pragma unroll
                for (int j = 0; j < 5; j++) {
                    float2 ep = unpack2(acc[i][j]);
                    float2 qv = qp[j];
                    float2 kv = kp[j];
                    part = fmaf(qv.x, kv.x + ep.x, part);
                    part = fmaf(qv.y, kv.y + ep.y, part);
                }
                atomicAdd(&apart[2 * r + h], part);
            }
        }
        __syncthreads();

        // ---- w = exp(alpha) (max-free), accumulate denominators ----
        for (int idx = tid; idx < 256; idx += TPB) {
            int r = idx >> 1, hh = idx & 1;
            int e = e0 + r;
            if (e < E) {
                float w = __expf(apart[idx] * inv);
                apart[idx] = w;                        // reuse as w_s
                atomicAdd(&g_aden[2 * didx[r] + hh], w);
            }
        }
        __syncthreads();

        // ---- scatter: AGGW[dst] += (v[src] + e_proj) * w  (vector REDs) ----
        #pragma unroll
        for (int i = 0; i < 8; i++) {
            int r = rb + i, e = e0 + r;
            if (e < E) {
                int s = sidx[r], d = didx[r];
                const float2* vp = (const float2*)(g_V + (size_t)s * 100 + cb);
                float w = apart[2 * r + h];
                float m[10];
                #pragma unroll
                for (int j = 0; j < 5; j++) {
                    float2 ep = unpack2(acc[i][j]);
                    float2 vv = vp[j];
                    m[2 * j]     = (vv.x + ep.x) * w;
                    m[2 * j + 1] = (vv.y + ep.y) * w;
                }
                float* op = g_AGGW + (size_t)d * 100 + cb;
                if ((cg & 1) == 0) {   // cb % 4 == 0 : 4+4+2
                    atomicAdd((float4*)op,       make_float4(m[0], m[1], m[2], m[3]));
                    atomicAdd((float4*)(op + 4), make_float4(m[4], m[5], m[6], m[7]));
                    atomicAdd((float2*)(op + 8), make_float2(m[8], m[9]));
                } else {               // cb % 4 == 2 : 2+4+4
                    atomicAdd((float2*)op,       make_float2(m[0], m[1]));
                    atomicAdd((float4*)(op + 2), make_float4(m[2], m[3], m[4], m[5]));
                    atomicAdd((float4*)(op + 6), make_float4(m[6], m[7], m[8], m[9]));
                }
            }
        }
    }
}

// =================================================================================
// link predictor with fused normalization:
// z_out = AGG(skip) + AGGW/aden ; out = relu(z_s@Ws^T + z_d@Wd^T + b) @ Wf^T + bf
// =================================================================================
__global__ void __launch_bounds__(128) linkpred_kernel(
    const float* __restrict__ Wsrc, const float* __restrict__ bsrc,
    const float* __restrict__ Wdst, const float* __restrict__ bdst,
    const float* __restrict__ Wf,   const float* __restrict__ bf,
    const int* __restrict__ src, const int* __restrict__ dst,
    float* __restrict__ out, int B)
{
    extern __shared__ float sm[];
    float* Ws   = sm;                 // [100][101] padded
    float* Wd   = Ws + 100 * 101;
    float* bsum = Wd + 100 * 101;
    float* wf   = bsum + 100;
    float* zrow = wf + 100;           // 4 warps * 200

    int tid = threadIdx.x, lane = tid & 31, warp = tid >> 5;
    for (int idx = tid; idx < 10000; idx += 128) {
        int o = idx / 100, k = idx - o * 100;
        Ws[o * 101 + k] = Wsrc[idx];
        Wd[o * 101 + k] = Wdst[idx];
    }
    if (tid < 100) { bsum[tid] = bsrc[tid] + bdst[tid]; wf[tid] = Wf[tid]; }
    __syncthreads();

    float bf0 = bf[0];
    float* zs = zrow + warp * 200;
    float* zd = zs + 100;

    for (int p = blockIdx.x * 4 + warp; p < B; p += gridDim.x * 4) {
        int sp = g_assoc[src[p]];
        int dp = g_assoc[dst[p]];
        float ds0 = g_aden[2 * sp], ds1 = g_aden[2 * sp + 1];
        float dd0 = g_aden[2 * dp], dd1 = g_aden[2 * dp + 1];
        float is0 = ds0 > 0.f ? 1.f / ds0 : 0.f;
        float is1 = ds1 > 0.f ? 1.f / ds1 : 0.f;
        float id0 = dd0 > 0.f ? 1.f / dd0 : 0.f;
        float id1 = dd1 > 0.f ? 1.f / dd1 : 0.f;
        for (int c = lane; c < 100; c += 32) {
            float invs = (c < 50) ? is0 : is1;
            float invd = (c < 50) ? id0 : id1;
            zs[c] = fmaf(g_AGGW[(size_t)sp * 100 + c], invs, g_AGG[(size_t)sp * 100 + c]);
            zd[c] = fmaf(g_AGGW[(size_t)dp * 100 + c], invd, g_AGG[(size_t)dp * 100 + c]);
        }
        __syncwarp();
        float acc = 0.f;
        for (int o = lane; o < 100; o += 32) {
            float hh = bsum[o];
            const float* wsr = Ws + o * 101;
            const float* wdr = Wd + o * 101;
            #pragma unroll 10
            for (int k = 0; k < 100; k++) {
                hh = fmaf(wsr[k], zs[k], hh);
                hh = fmaf(wdr[k], zd[k], hh);
            }
            hh = fmaxf(hh, 0.f);
            acc = fmaf(hh, wf[o], acc);
        }
        #pragma unroll
        for (int o = 16; o; o >>= 1) acc += __shfl_xor_sync(0xffffffffu, acc, o);
        if (lane == 0) out[p] = acc + bf0;
        __syncwarp();
    }
}

// ---------------- launch ----------------------------------------------------------
extern "C" void kernel_launch(void* const* d_in, const int* in_sizes, int n_in,
                              void* d_out, int out_size)
{
    const float* z     = (const float*)d_in[0];
    const float* lu    = (const float*)d_in[1];
    const float* t     = (const float*)d_in[2];
    const float* msg   = (const float*)d_in[3];
    const float* tw    = (const float*)d_in[4];
    const float* tb    = (const float*)d_in[5];
    const float* Wq    = (const float*)d_in[6];
    const float* bq    = (const float*)d_in[7];
    const float* Wk    = (const float*)d_in[8];
    const float* bk    = (const float*)d_in[9];
    const float* Wv    = (const float*)d_in[10];
    const float* bv    = (const float*)d_in[11];
    const float* We    = (const float*)d_in[12];
    const float* Wskip = (const float*)d_in[13];
    const float* bskip = (const float*)d_in[14];
    const float* Wsrc  = (const float*)d_in[15];
    const float* bsrc  = (const float*)d_in[16];
    const float* Wdst  = (const float*)d_in[17];
    const float* bdst  = (const float*)d_in[18];
    const float* Wf    = (const float*)d_in[19];
    const float* bf    = (const float*)d_in[20];
    const int*   n_id  = (const int*)d_in[21];
    const int*   srcp  = (const int*)d_in[22];
    const int*   dstp  = (const int*)d_in[23];
    const int*   ei    = (const int*)d_in[24];

    int N = in_sizes[0] / 100;
    int E = in_sizes[2];
    int B = in_sizes[22];
    float* out = (float*)d_out;

    int ntilesN = (N + 127) / 128;
    int ntilesE = (E + 127) / 128;

    const int SMEM_QKVS = (10000 + 50 * SA + 100) * 4;                        // ~66.8 KB
    const int SMEM_EDGE = (10100 + 51 * SA + 100 + 100 + 128 + 128 + 256
                           + 128 + 128) * 4;                                  // ~71.2 KB
    const int SMEM_LP   = (2 * 100 * 101 + 200 + 4 * 200) * 4;                // ~84.8 KB

    cudaFuncSetAttribute(qkvs_kernel,     cudaFuncAttributeMaxDynamicSharedMemorySize, SMEM_QKVS);
    cudaFuncSetAttribute(edge_kernel,     cudaFuncAttributeMaxDynamicSharedMemorySize, SMEM_EDGE);
    cudaFuncSetAttribute(linkpred_kernel, cudaFuncAttributeMaxDynamicSharedMemorySize, SMEM_LP);

    init_kernel<<<(N * 25 + 255) / 256, 256>>>(N);
    assoc_kernel<<<(N + 255) / 256, 256>>>(n_id, N);

    dim3 gq(111, 4);   // 444 persistent CTAs (148 SMs x 3)
    qkvs_kernel<<<gq, TPB, SMEM_QKVS>>>(z, Wq, bq, Wk, bk, Wv, bv, Wskip, bskip,
                                        N, ntilesN);

    edge_kernel<<<444, TPB, SMEM_EDGE>>>(lu, t, msg, tw, tb, We, ei, E, ntilesE);

    linkpred_kernel<<<296, 128, SMEM_LP>>>(Wsrc, bsrc, Wdst, bdst, Wf, bf,
                                           srcp, dstp, out, B);
}